// round 1
// baseline (speedup 1.0000x reference)
#include <cuda_runtime.h>
#include <cuda_bf16.h>
#include <mma.h>

using namespace nvcuda;

// Problem constants
#define NN 4096
#define EMB 128
#define HH 128
#define EE 8
#define TT 2

// Scratch (device globals; no allocations allowed)
__device__ float g_X0[NN * 384];
__device__ float g_h0[NN * HH];
__device__ float g_h1[NN * HH];
__device__ float g_ho[EE * NN * HH];
__device__ float g_hi[EE * NN * HH];
__device__ float g_msg[NN * 2 * EE * HH];   // [N, 2048]
__device__ float g_gi[NN * 3 * HH];         // [N, 384]
__device__ float g_gh[NN * 3 * HH];

// ---------------------------------------------------------------------------
// gather + concat: X0[n, 0:128] = emb[ids[n]], X0[n,128:384] = states[n]
// ---------------------------------------------------------------------------
__global__ void gather_concat_kernel(const float* __restrict__ emb,
                                     const int* __restrict__ ids,
                                     const float* __restrict__ states,
                                     float* __restrict__ X0) {
    int i = blockIdx.x * blockDim.x + threadIdx.x;
    if (i >= NN * 384) return;
    int n = i / 384, c = i % 384;
    X0[i] = (c < EMB) ? emb[(long)ids[n] * EMB + c]
                      : states[(long)n * (2 * EMB) + (c - EMB)];
}

// ---------------------------------------------------------------------------
// elementwise: x = tanh(x + bias[batch, col])
// ---------------------------------------------------------------------------
__global__ void bias_tanh_kernel(float* __restrict__ x,
                                 const float* __restrict__ bias,
                                 int total, int cols, int perBatch) {
    int i = blockIdx.x * blockDim.x + threadIdx.x;
    if (i >= total) return;
    int k = i % cols;
    int e = i / perBatch;
    x[i] = tanhf(x[i] + bias[e * cols + k]);
}

// ---------------------------------------------------------------------------
// Split-bf16 GEMM: C = op(A) @ B, fp32 in/out, 3x bf16 HMMA accumulation.
// BM=128, BN=128, BK=32, 256 threads (8 warps: 4 along M x 2 along N).
// Requires: M % 128 == 0, Ncols % 128 == 0, K % 32 == 0 (all hold here).
// ---------------------------------------------------------------------------
__device__ __forceinline__ void split_bf16(float x, __nv_bfloat16& h, __nv_bfloat16& l) {
    h = __float2bfloat16(x);
    l = __float2bfloat16(x - __bfloat162float(h));
}

__global__ __launch_bounds__(256)
void gemm_bf16x3_kernel(const float* __restrict__ A,
                        const float* __restrict__ B,
                        float* __restrict__ C,
                        int K, int lda, int ldb, int ldc, int transA,
                        long sA, long sB, long sC) {
    A += (long)blockIdx.z * sA;
    B += (long)blockIdx.z * sB;
    C += (long)blockIdx.z * sC;

    const int i0 = blockIdx.x * 128;
    const int j0 = blockIdx.y * 128;

    __shared__ __nv_bfloat16 Ah[128][40];
    __shared__ __nv_bfloat16 Al[128][40];
    __shared__ __nv_bfloat16 Bh[32][136];
    __shared__ __nv_bfloat16 Bl[32][136];

    const int tid  = threadIdx.x;
    const int warp = tid >> 5;
    const int wm   = warp & 3;   // 0..3 (M)
    const int wn   = warp >> 2;  // 0..1 (N)

    wmma::fragment<wmma::accumulator, 16, 16, 16, float> acc[2][4];
#pragma unroll
    for (int m = 0; m < 2; m++)
#pragma unroll
        for (int n = 0; n < 4; n++)
            wmma::fill_fragment(acc[m][n], 0.0f);

    for (int k0 = 0; k0 < K; k0 += 32) {
        // ---- load A tile (128 x 32) as hi/lo bf16 ----
        if (!transA) {
#pragma unroll
            for (int it = 0; it < 4; it++) {
                int idx = tid + it * 256;           // 1024 float4s
                int r   = idx >> 3;
                int c4  = (idx & 7) * 4;
                float4 v = *(const float4*)(A + (long)(i0 + r) * lda + k0 + c4);
                float xs[4] = {v.x, v.y, v.z, v.w};
#pragma unroll
                for (int j = 0; j < 4; j++) {
                    __nv_bfloat16 h, l;
                    split_bf16(xs[j], h, l);
                    Ah[r][c4 + j] = h;
                    Al[r][c4 + j] = l;
                }
            }
        } else {
            // C[i,k] = sum_m A[m,i] * B[m,k]; read rows of A (contiguous in i)
#pragma unroll
            for (int it = 0; it < 4; it++) {
                int idx = tid + it * 256;
                int kk  = idx >> 5;                 // 0..31
                int m4  = (idx & 31) * 4;           // 0..124
                float4 v = *(const float4*)(A + (long)(k0 + kk) * lda + i0 + m4);
                float xs[4] = {v.x, v.y, v.z, v.w};
#pragma unroll
                for (int j = 0; j < 4; j++) {
                    __nv_bfloat16 h, l;
                    split_bf16(xs[j], h, l);
                    Ah[m4 + j][kk] = h;
                    Al[m4 + j][kk] = l;
                }
            }
        }
        // ---- load B tile (32 x 128) as hi/lo bf16 ----
#pragma unroll
        for (int it = 0; it < 4; it++) {
            int idx = tid + it * 256;
            int kk  = idx >> 5;
            int n4  = (idx & 31) * 4;
            float4 v = *(const float4*)(B + (long)(k0 + kk) * ldb + j0 + n4);
            float xs[4] = {v.x, v.y, v.z, v.w};
#pragma unroll
            for (int j = 0; j < 4; j++) {
                __nv_bfloat16 h, l;
                split_bf16(xs[j], h, l);
                Bh[kk][n4 + j] = h;
                Bl[kk][n4 + j] = l;
            }
        }
        __syncthreads();

#pragma unroll
        for (int ks = 0; ks < 32; ks += 16) {
            wmma::fragment<wmma::matrix_a, 16, 16, 16, __nv_bfloat16, wmma::row_major> ah[2], al[2];
#pragma unroll
            for (int m = 0; m < 2; m++) {
                wmma::load_matrix_sync(ah[m], &Ah[wm * 32 + m * 16][ks], 40);
                wmma::load_matrix_sync(al[m], &Al[wm * 32 + m * 16][ks], 40);
            }
#pragma unroll
            for (int n = 0; n < 4; n++) {
                wmma::fragment<wmma::matrix_b, 16, 16, 16, __nv_bfloat16, wmma::row_major> bh_, bl_;
                wmma::load_matrix_sync(bh_, &Bh[ks][wn * 64 + n * 16], 136);
                wmma::load_matrix_sync(bl_, &Bl[ks][wn * 64 + n * 16], 136);
#pragma unroll
                for (int m = 0; m < 2; m++) {
                    wmma::mma_sync(acc[m][n], ah[m], bh_, acc[m][n]);
                    wmma::mma_sync(acc[m][n], ah[m], bl_, acc[m][n]);
                    wmma::mma_sync(acc[m][n], al[m], bh_, acc[m][n]);
                }
            }
        }
        __syncthreads();
    }

#pragma unroll
    for (int m = 0; m < 2; m++)
#pragma unroll
        for (int n = 0; n < 4; n++)
            wmma::store_matrix_sync(
                C + (long)(i0 + wm * 32 + m * 16) * ldc + j0 + wn * 64 + n * 16,
                acc[m][n], ldc, wmma::mem_row_major);
}

// ---------------------------------------------------------------------------
// GRU + LayerNorm, one block per node row, 128 threads
// ---------------------------------------------------------------------------
__device__ __forceinline__ float block_sum128(float v, float* red) {
#pragma unroll
    for (int o = 16; o; o >>= 1) v += __shfl_xor_sync(0xffffffffu, v, o);
    int lane = threadIdx.x & 31, w = threadIdx.x >> 5;
    if (lane == 0) red[w] = v;
    __syncthreads();
    float s = red[0] + red[1] + red[2] + red[3];
    __syncthreads();
    return s;
}

__global__ void gru_kernel(const float* __restrict__ gi, const float* __restrict__ gh,
                           const float* __restrict__ h,
                           const float* __restrict__ bx, const float* __restrict__ bh,
                           const float* __restrict__ gamma, const float* __restrict__ beta,
                           float* __restrict__ out) {
    __shared__ float red[4];
    const int n = blockIdx.x;
    const int k = threadIdx.x;

    float gi0 = gi[(long)n * 384 + k];
    float gi1 = gi[(long)n * 384 + 128 + k];
    float gi2 = gi[(long)n * 384 + 256 + k];
    float gh0 = gh[(long)n * 384 + k];
    float gh1 = gh[(long)n * 384 + 128 + k];
    float gh2 = gh[(long)n * 384 + 256 + k];

    float xr = gi0 + bx[k]       + gh0 + bh[k];
    float xz = gi1 + bx[128 + k] + gh1 + bh[128 + k];
    float xi = gi2 + bx[256 + k];
    float xh = gh2 + bh[256 + k];

    // LN + sigmoid for r
    float mean = block_sum128(xr, red) * (1.0f / 128.0f);
    float d = xr - mean;
    float var = block_sum128(d * d, red) * (1.0f / 128.0f);
    float yr = d * rsqrtf(var + 1e-5f) * gamma[k] + beta[k];
    float r = 1.0f / (1.0f + expf(-yr));

    // LN + sigmoid for z
    mean = block_sum128(xz, red) * (1.0f / 128.0f);
    d = xz - mean;
    var = block_sum128(d * d, red) * (1.0f / 128.0f);
    float yz = d * rsqrtf(var + 1e-5f) * gamma[128 + k] + beta[128 + k];
    float z = 1.0f / (1.0f + expf(-yz));

    // LN + tanh for n
    float xn = xi + r * xh;
    mean = block_sum128(xn, red) * (1.0f / 128.0f);
    d = xn - mean;
    var = block_sum128(d * d, red) * (1.0f / 128.0f);
    float yn = d * rsqrtf(var + 1e-5f) * gamma[256 + k] + beta[256 + k];
    float nn = tanhf(yn);

    float hv = h[(long)n * 128 + k];
    out[(long)n * 128 + k] = (1.0f - z) * nn + z * hv;
}

// ---------------------------------------------------------------------------
// launch
// ---------------------------------------------------------------------------
extern "C" void kernel_launch(void* const* d_in, const int* in_sizes, int n_in,
                              void* d_out, int out_size) {
    (void)in_sizes; (void)n_in; (void)out_size;

    const float* adj     = (const float*)d_in[0];
    const float* states  = (const float*)d_in[1];
    const int*   ids     = (const int*)  d_in[2];
    const float* emb     = (const float*)d_in[3];
    const float* W_init  = (const float*)d_in[4];
    const float* b_init  = (const float*)d_in[5];
    const float* W_out   = (const float*)d_in[6];
    const float* b_out   = (const float*)d_in[7];
    const float* W_in    = (const float*)d_in[8];
    const float* b_in    = (const float*)d_in[9];
    const float* Wx      = (const float*)d_in[10];
    const float* bx      = (const float*)d_in[11];
    const float* Wh      = (const float*)d_in[12];
    const float* bh      = (const float*)d_in[13];
    const float* gamma   = (const float*)d_in[14];
    const float* beta    = (const float*)d_in[15];
    float* out = (float*)d_out;

    float *X0, *h0, *h1, *ho, *hi, *msg, *gi, *gh;
    cudaGetSymbolAddress((void**)&X0,  g_X0);
    cudaGetSymbolAddress((void**)&h0,  g_h0);
    cudaGetSymbolAddress((void**)&h1,  g_h1);
    cudaGetSymbolAddress((void**)&ho,  g_ho);
    cudaGetSymbolAddress((void**)&hi,  g_hi);
    cudaGetSymbolAddress((void**)&msg, g_msg);
    cudaGetSymbolAddress((void**)&gi,  g_gi);
    cudaGetSymbolAddress((void**)&gh,  g_gh);

    // h0 = tanh(X0 @ W_init + b_init)
    gather_concat_kernel<<<(NN * 384 + 255) / 256, 256>>>(emb, ids, states, X0);
    gemm_bf16x3_kernel<<<dim3(NN / 128, 1, 1), 256>>>(X0, W_init, h0,
                                                      384, 384, 128, 128, 0, 0, 0, 0);
    bias_tanh_kernel<<<(NN * HH) / 256, 256>>>(h0, b_init, NN * HH, HH, NN * HH);

    const float* hcur = h0;
    for (int t = 0; t < TT; t++) {
        // per-edge transforms: ho[e] = tanh(h @ W_out[e] + b_out[e]); hi likewise
        gemm_bf16x3_kernel<<<dim3(NN / 128, 1, EE), 256>>>(hcur, W_out, ho,
                                                           HH, HH, HH, HH, 0,
                                                           0, (long)HH * HH, (long)NN * HH);
        bias_tanh_kernel<<<(EE * NN * HH) / 256, 256>>>(ho, b_out, EE * NN * HH, HH, NN * HH);
        gemm_bf16x3_kernel<<<dim3(NN / 128, 1, EE), 256>>>(hcur, W_in, hi,
                                                           HH, HH, HH, HH, 0,
                                                           0, (long)HH * HH, (long)NN * HH);
        bias_tanh_kernel<<<(EE * NN * HH) / 256, 256>>>(hi, b_in, EE * NN * HH, HH, NN * HH);

        // messages: mo = A[e] @ ho[e] -> msg[:, e*128 :], mi = A[e]^T @ hi[e] -> msg[:, 1024 + e*128 :]
        gemm_bf16x3_kernel<<<dim3(NN / 128, 1, EE), 256>>>(adj, ho, msg,
                                                           NN, NN, HH, 2 * EE * HH, 0,
                                                           (long)NN * NN, (long)NN * HH, (long)HH);
        gemm_bf16x3_kernel<<<dim3(NN / 128, 1, EE), 256>>>(adj, hi, msg + EE * HH,
                                                           NN, NN, HH, 2 * EE * HH, 1,
                                                           (long)NN * NN, (long)NN * HH, (long)HH);

        // GRU pre-activations (biases folded into gru_kernel)
        gemm_bf16x3_kernel<<<dim3(NN / 128, 3, 1), 256>>>(msg, Wx, gi,
                                                          2 * EE * HH, 2 * EE * HH, 3 * HH, 3 * HH, 0,
                                                          0, 0, 0);
        gemm_bf16x3_kernel<<<dim3(NN / 128, 3, 1), 256>>>(hcur, Wh, gh,
                                                          HH, HH, 3 * HH, 3 * HH, 0,
                                                          0, 0, 0);

        float* hnext = (t == TT - 1) ? out : h1;
        gru_kernel<<<NN, 128>>>(gi, gh, hcur, bx, bh, gamma, beta, hnext);
        hcur = h1;
    }
}

// round 2
// speedup vs baseline: 1.8146x; 1.8146x over previous
#include <cuda_runtime.h>
#include <cuda_bf16.h>
#include <mma.h>

using namespace nvcuda;

#define NN 4096
#define EMB 128
#define HH 128
#define EE 8
#define TT 2

typedef __nv_bfloat16 bf16;

// ---------------------------------------------------------------------------
// Scratch (device globals; allocation-free)
// ---------------------------------------------------------------------------
__device__ bf16 g_adjH[(long)EE * NN * NN];
__device__ bf16 g_adjL[(long)EE * NN * NN];
__device__ bf16 g_hoH[EE * NN * HH], g_hoL[EE * NN * HH];
__device__ bf16 g_hiH[EE * NN * HH], g_hiL[EE * NN * HH];
__device__ bf16 g_msgH[NN * 2048], g_msgL[NN * 2048];
__device__ bf16 g_hH[NN * HH], g_hL[NN * HH];
__device__ bf16 g_X0H[NN * 384], g_X0L[NN * 384];
__device__ bf16 g_WinitH[384 * HH], g_WinitL[384 * HH];
__device__ bf16 g_WoutH[EE * HH * HH], g_WoutL[EE * HH * HH];
__device__ bf16 g_WinH[EE * HH * HH], g_WinL[EE * HH * HH];
__device__ bf16 g_WxH[2048 * 384], g_WxL[2048 * 384];
__device__ bf16 g_WhH[HH * 384], g_WhL[HH * 384];
__device__ float g_hf[NN * HH];
__device__ float g_gi[NN * 384], g_gh[NN * 384];

__device__ __forceinline__ void split_bf16(float x, bf16& h, bf16& l) {
    h = __float2bfloat16(x);
    l = __float2bfloat16(x - __bfloat162float(h));
}

__device__ __forceinline__ void cp16(bf16* dst, const bf16* src) {
    unsigned d = (unsigned)__cvta_generic_to_shared(dst);
    asm volatile("cp.async.cg.shared.global [%0], [%1], 16;" :: "r"(d), "l"(src));
}
__device__ __forceinline__ void cp_commit() { asm volatile("cp.async.commit_group;"); }
template <int N> __device__ __forceinline__ void cp_wait() {
    asm volatile("cp.async.wait_group %0;" :: "n"(N));
}

// ---------------------------------------------------------------------------
// fp32 -> split bf16 conversion (vectorized, 4 elems/thread)
// ---------------------------------------------------------------------------
__global__ void split_kernel(const float4* __restrict__ x,
                             uint2* __restrict__ hOut, uint2* __restrict__ lOut,
                             long n4) {
    long i = (long)blockIdx.x * blockDim.x + threadIdx.x;
    if (i >= n4) return;
    float4 v = x[i];
    float vv[4] = {v.x, v.y, v.z, v.w};
    union { bf16 b[4]; uint2 u; } ph, pl;
#pragma unroll
    for (int j = 0; j < 4; j++) split_bf16(vv[j], ph.b[j], pl.b[j]);
    hOut[i] = ph.u;
    lOut[i] = pl.u;
}

// ---------------------------------------------------------------------------
// gather + concat -> split bf16 X0
// ---------------------------------------------------------------------------
__global__ void gather_concat_kernel(const float* __restrict__ emb,
                                     const int* __restrict__ ids,
                                     const float* __restrict__ states,
                                     bf16* __restrict__ XH, bf16* __restrict__ XL) {
    int i = blockIdx.x * blockDim.x + threadIdx.x;
    if (i >= NN * 384) return;
    int n = i / 384, c = i % 384;
    float v = (c < EMB) ? emb[(long)ids[n] * EMB + c]
                        : states[(long)n * (2 * EMB) + (c - EMB)];
    bf16 h, l;
    split_bf16(v, h, l);
    XH[i] = h;
    XL[i] = l;
}

// ---------------------------------------------------------------------------
// Pipelined split-bf16 GEMM, BM=BN=128, BK=32, 4 stages, 256 threads.
// modes: 0=fp32 C; 1=tanh(acc+bias)->split bf16; 2=split bf16; 3=tanh->fp32+split
// dual: z in [0,16), z>=8 uses B2/bias2/C2 and (optionally) transA.
// ---------------------------------------------------------------------------
struct GP {
    const bf16 *AH, *AL, *B1H, *B1L, *B2H, *B2L;
    const float *bias1, *bias2;
    float* C;
    bf16 *C1H, *C1L, *C2H, *C2L;
    int K, lda, ldb, ldc;
    long sA, sB, sC;
    int dual, trans2, mode;
    int coff1, coff2, cstride, biasStride;
};

#define STAGES 4
#define ASZ 5120     // elems: max(128*40, 32*136)
#define BSZ 4352     // elems: 32*136
#define STG (2 * ASZ + 2 * BSZ)
#define SMEM_BYTES (STAGES * STG * 2)

__global__ __launch_bounds__(256)
void gemm_k(GP p) {
    extern __shared__ char smemraw[];
    bf16* sm = (bf16*)smemraw;

    const int z = blockIdx.z;
    const bool second = p.dual && (z >= 8);
    const int e = p.dual ? (z & 7) : z;
    const int trans = second ? p.trans2 : 0;

    const bf16* AH = p.AH + (long)e * p.sA;
    const bf16* AL = p.AL + (long)e * p.sA;
    const bf16* BH = (second ? p.B2H : p.B1H) + (long)e * p.sB;
    const bf16* BL = (second ? p.B2L : p.B1L) + (long)e * p.sB;

    const int i0 = blockIdx.x * 128;
    const int j0 = blockIdx.y * 128;
    const int tid = threadIdx.x;
    const int wm = (tid >> 5) & 3;
    const int wn = tid >> 7;

    auto loadStage = [&](int s, int k0) {
        bf16* aH = sm + s * STG;
        bf16* aL = aH + ASZ;
        bf16* bH = aL + ASZ;
        bf16* bL = bH + BSZ;
        if (!trans) {
#pragma unroll
            for (int t = 0; t < 2; t++) {
                int idx = tid + t * 256;
                int r = idx >> 2, c = (idx & 3) * 8;
                cp16(aH + r * 40 + c, AH + (long)(i0 + r) * p.lda + k0 + c);
                cp16(aL + r * 40 + c, AL + (long)(i0 + r) * p.lda + k0 + c);
            }
        } else {
#pragma unroll
            for (int t = 0; t < 2; t++) {
                int idx = tid + t * 256;
                int r = idx >> 4, c = (idx & 15) * 8;
                cp16(aH + r * 136 + c, AH + (long)(k0 + r) * p.lda + i0 + c);
                cp16(aL + r * 136 + c, AL + (long)(k0 + r) * p.lda + i0 + c);
            }
        }
#pragma unroll
        for (int t = 0; t < 2; t++) {
            int idx = tid + t * 256;
            int r = idx >> 4, c = (idx & 15) * 8;
            cp16(bH + r * 136 + c, BH + (long)(k0 + r) * p.ldb + j0 + c);
            cp16(bL + r * 136 + c, BL + (long)(k0 + r) * p.ldb + j0 + c);
        }
    };

    wmma::fragment<wmma::accumulator, 16, 16, 16, float> acc[2][4];
#pragma unroll
    for (int m = 0; m < 2; m++)
#pragma unroll
        for (int n = 0; n < 4; n++)
            wmma::fill_fragment(acc[m][n], 0.0f);

    const int kIters = p.K / 32;
    for (int s = 0; s < STAGES - 1 && s < kIters; s++) {
        loadStage(s, s * 32);
        cp_commit();
    }

    for (int ki = 0; ki < kIters; ki++) {
        cp_wait<STAGES - 2>();
        __syncthreads();
        int ns = ki + STAGES - 1;
        if (ns < kIters) loadStage(ns % STAGES, ns * 32);
        cp_commit();

        bf16* aHB = sm + (ki % STAGES) * STG;
        bf16* aLB = aHB + ASZ;
        bf16* bHB = aLB + ASZ;
        bf16* bLB = bHB + BSZ;

        if (!trans) {
#pragma unroll
            for (int ks = 0; ks < 32; ks += 16) {
                wmma::fragment<wmma::matrix_a, 16, 16, 16, bf16, wmma::row_major> ah[2], al[2];
#pragma unroll
                for (int m = 0; m < 2; m++) {
                    wmma::load_matrix_sync(ah[m], aHB + (wm * 32 + m * 16) * 40 + ks, 40);
                    wmma::load_matrix_sync(al[m], aLB + (wm * 32 + m * 16) * 40 + ks, 40);
                }
#pragma unroll
                for (int n = 0; n < 4; n++) {
                    wmma::fragment<wmma::matrix_b, 16, 16, 16, bf16, wmma::row_major> bh_, bl_;
                    wmma::load_matrix_sync(bh_, bHB + ks * 136 + wn * 64 + n * 16, 136);
                    wmma::load_matrix_sync(bl_, bLB + ks * 136 + wn * 64 + n * 16, 136);
#pragma unroll
                    for (int m = 0; m < 2; m++) {
                        wmma::mma_sync(acc[m][n], ah[m], bh_, acc[m][n]);
                        wmma::mma_sync(acc[m][n], ah[m], bl_, acc[m][n]);
                        wmma::mma_sync(acc[m][n], al[m], bh_, acc[m][n]);
                    }
                }
            }
        } else {
#pragma unroll
            for (int ks = 0; ks < 32; ks += 16) {
                wmma::fragment<wmma::matrix_a, 16, 16, 16, bf16, wmma::col_major> ah[2], al[2];
#pragma unroll
                for (int m = 0; m < 2; m++) {
                    wmma::load_matrix_sync(ah[m], aHB + ks * 136 + wm * 32 + m * 16, 136);
                    wmma::load_matrix_sync(al[m], aLB + ks * 136 + wm * 32 + m * 16, 136);
                }
#pragma unroll
                for (int n = 0; n < 4; n++) {
                    wmma::fragment<wmma::matrix_b, 16, 16, 16, bf16, wmma::row_major> bh_, bl_;
                    wmma::load_matrix_sync(bh_, bHB + ks * 136 + wn * 64 + n * 16, 136);
                    wmma::load_matrix_sync(bl_, bLB + ks * 136 + wn * 64 + n * 16, 136);
#pragma unroll
                    for (int m = 0; m < 2; m++) {
                        wmma::mma_sync(acc[m][n], ah[m], bh_, acc[m][n]);
                        wmma::mma_sync(acc[m][n], ah[m], bl_, acc[m][n]);
                        wmma::mma_sync(acc[m][n], al[m], bh_, acc[m][n]);
                    }
                }
            }
        }
    }

    // ---- epilogue (reuse pipeline smem as fp32 staging [128][132]) ----
    cp_wait<0>();
    __syncthreads();
    float* st = (float*)smemraw;
#pragma unroll
    for (int m = 0; m < 2; m++)
#pragma unroll
        for (int n = 0; n < 4; n++)
            wmma::store_matrix_sync(st + (wm * 32 + m * 16) * 132 + wn * 64 + n * 16,
                                    acc[m][n], 132, wmma::mem_row_major);
    __syncthreads();

    const int colOff = (second ? p.coff2 : p.coff1) + e * p.cstride + j0;
    const long cbase = (long)e * p.sC;
    const float* bias = second ? p.bias2 : p.bias1;
    bf16* CH = (second && p.C2H) ? p.C2H : p.C1H;
    bf16* CL = (second && p.C2L) ? p.C2L : p.C1L;

#pragma unroll
    for (int t = 0; t < 16; t++) {
        int idx = tid + t * 256;
        int r = idx >> 5, c = (idx & 31) * 4;
        float4 v = *(float4*)(st + r * 132 + c);
        float vv[4] = {v.x, v.y, v.z, v.w};
        if (p.mode == 1 || p.mode == 3) {
#pragma unroll
            for (int j = 0; j < 4; j++)
                vv[j] = tanhf(vv[j] + bias[e * p.biasStride + j0 + c + j]);
        }
        long row = cbase + (long)(i0 + r) * p.ldc + colOff + c;
        if (p.mode == 0 || p.mode == 3)
            *(float4*)(p.C + row) = make_float4(vv[0], vv[1], vv[2], vv[3]);
        if (p.mode != 0) {
            union { bf16 b[4]; uint2 u; } ph, pl;
#pragma unroll
            for (int j = 0; j < 4; j++) split_bf16(vv[j], ph.b[j], pl.b[j]);
            *(uint2*)(CH + row) = ph.u;
            *(uint2*)(CL + row) = pl.u;
        }
    }
}

// ---------------------------------------------------------------------------
// GRU + LayerNorm, one block per node row, 128 threads
// ---------------------------------------------------------------------------
__device__ __forceinline__ float block_sum128(float v, float* red) {
#pragma unroll
    for (int o = 16; o; o >>= 1) v += __shfl_xor_sync(0xffffffffu, v, o);
    int lane = threadIdx.x & 31, w = threadIdx.x >> 5;
    if (lane == 0) red[w] = v;
    __syncthreads();
    float s = red[0] + red[1] + red[2] + red[3];
    __syncthreads();
    return s;
}

__global__ void gru_kernel(const float* __restrict__ gi, const float* __restrict__ gh,
                           const float* __restrict__ h,
                           const float* __restrict__ bx, const float* __restrict__ bh,
                           const float* __restrict__ gamma, const float* __restrict__ beta,
                           float* __restrict__ out,
                           bf16* __restrict__ outH, bf16* __restrict__ outL) {
    __shared__ float red[4];
    const int n = blockIdx.x;
    const int k = threadIdx.x;

    float gi0 = gi[(long)n * 384 + k];
    float gi1 = gi[(long)n * 384 + 128 + k];
    float gi2 = gi[(long)n * 384 + 256 + k];
    float gh0 = gh[(long)n * 384 + k];
    float gh1 = gh[(long)n * 384 + 128 + k];
    float gh2 = gh[(long)n * 384 + 256 + k];

    float xr = gi0 + bx[k]       + gh0 + bh[k];
    float xz = gi1 + bx[128 + k] + gh1 + bh[128 + k];
    float xi = gi2 + bx[256 + k];
    float xh = gh2 + bh[256 + k];

    float mean = block_sum128(xr, red) * (1.0f / 128.0f);
    float d = xr - mean;
    float var = block_sum128(d * d, red) * (1.0f / 128.0f);
    float yr = d * rsqrtf(var + 1e-5f) * gamma[k] + beta[k];
    float r = 1.0f / (1.0f + expf(-yr));

    mean = block_sum128(xz, red) * (1.0f / 128.0f);
    d = xz - mean;
    var = block_sum128(d * d, red) * (1.0f / 128.0f);
    float yz = d * rsqrtf(var + 1e-5f) * gamma[128 + k] + beta[128 + k];
    float z = 1.0f / (1.0f + expf(-yz));

    float xn = xi + r * xh;
    mean = block_sum128(xn, red) * (1.0f / 128.0f);
    d = xn - mean;
    var = block_sum128(d * d, red) * (1.0f / 128.0f);
    float yn = d * rsqrtf(var + 1e-5f) * gamma[256 + k] + beta[256 + k];
    float nn_ = tanhf(yn);

    float hv = h[(long)n * 128 + k];
    float o = (1.0f - z) * nn_ + z * hv;
    out[(long)n * 128 + k] = o;
    bf16 hh, ll;
    split_bf16(o, hh, ll);
    outH[(long)n * 128 + k] = hh;
    outL[(long)n * 128 + k] = ll;
}

// ---------------------------------------------------------------------------
// launch
// ---------------------------------------------------------------------------
static inline GP zeroGP() { GP p; memset(&p, 0, sizeof(p)); return p; }

extern "C" void kernel_launch(void* const* d_in, const int* in_sizes, int n_in,
                              void* d_out, int out_size) {
    (void)in_sizes; (void)n_in; (void)out_size;

    const float* adj    = (const float*)d_in[0];
    const float* states = (const float*)d_in[1];
    const int*   ids    = (const int*)  d_in[2];
    const float* emb    = (const float*)d_in[3];
    const float* W_init = (const float*)d_in[4];
    const float* b_init = (const float*)d_in[5];
    const float* W_out  = (const float*)d_in[6];
    const float* b_out  = (const float*)d_in[7];
    const float* W_in   = (const float*)d_in[8];
    const float* b_in   = (const float*)d_in[9];
    const float* Wx     = (const float*)d_in[10];
    const float* bx     = (const float*)d_in[11];
    const float* Wh     = (const float*)d_in[12];
    const float* bh     = (const float*)d_in[13];
    const float* gamma  = (const float*)d_in[14];
    const float* beta   = (const float*)d_in[15];
    float* out = (float*)d_out;

    bf16 *adjH, *adjL, *hoH, *hoL, *hiH, *hiL, *msgH, *msgL, *hH, *hL;
    bf16 *X0H, *X0L, *WinitH, *WinitL, *WoutH, *WoutL, *WinH, *WinL;
    bf16 *WxH, *WxL, *WhH, *WhL;
    float *hf, *gi, *gh;
    cudaGetSymbolAddress((void**)&adjH, g_adjH);
    cudaGetSymbolAddress((void**)&adjL, g_adjL);
    cudaGetSymbolAddress((void**)&hoH, g_hoH);
    cudaGetSymbolAddress((void**)&hoL, g_hoL);
    cudaGetSymbolAddress((void**)&hiH, g_hiH);
    cudaGetSymbolAddress((void**)&hiL, g_hiL);
    cudaGetSymbolAddress((void**)&msgH, g_msgH);
    cudaGetSymbolAddress((void**)&msgL, g_msgL);
    cudaGetSymbolAddress((void**)&hH, g_hH);
    cudaGetSymbolAddress((void**)&hL, g_hL);
    cudaGetSymbolAddress((void**)&X0H, g_X0H);
    cudaGetSymbolAddress((void**)&X0L, g_X0L);
    cudaGetSymbolAddress((void**)&WinitH, g_WinitH);
    cudaGetSymbolAddress((void**)&WinitL, g_WinitL);
    cudaGetSymbolAddress((void**)&WoutH, g_WoutH);
    cudaGetSymbolAddress((void**)&WoutL, g_WoutL);
    cudaGetSymbolAddress((void**)&WinH, g_WinH);
    cudaGetSymbolAddress((void**)&WinL, g_WinL);
    cudaGetSymbolAddress((void**)&WxH, g_WxH);
    cudaGetSymbolAddress((void**)&WxL, g_WxL);
    cudaGetSymbolAddress((void**)&WhH, g_WhH);
    cudaGetSymbolAddress((void**)&WhL, g_WhL);
    cudaGetSymbolAddress((void**)&hf, g_hf);
    cudaGetSymbolAddress((void**)&gi, g_gi);
    cudaGetSymbolAddress((void**)&gh, g_gh);

    cudaFuncSetAttribute(gemm_k, cudaFuncAttributeMaxDynamicSharedMemorySize, SMEM_BYTES);

    // ---- preconvert operands to split bf16 ----
    {
        long n4 = (long)EE * NN * NN / 4;
        split_kernel<<<(unsigned)((n4 + 255) / 256), 256>>>((const float4*)adj, (uint2*)adjH, (uint2*)adjL, n4);
    }
    split_kernel<<<(384 * HH / 4 + 255) / 256, 256>>>((const float4*)W_init, (uint2*)WinitH, (uint2*)WinitL, 384 * HH / 4);
    split_kernel<<<(EE * HH * HH / 4 + 255) / 256, 256>>>((const float4*)W_out, (uint2*)WoutH, (uint2*)WoutL, EE * HH * HH / 4);
    split_kernel<<<(EE * HH * HH / 4 + 255) / 256, 256>>>((const float4*)W_in, (uint2*)WinH, (uint2*)WinL, EE * HH * HH / 4);
    split_kernel<<<(2048 * 384 / 4 + 255) / 256, 256>>>((const float4*)Wx, (uint2*)WxH, (uint2*)WxL, 2048 * 384 / 4);
    split_kernel<<<(HH * 384 / 4 + 255) / 256, 256>>>((const float4*)Wh, (uint2*)WhH, (uint2*)WhL, HH * 384 / 4);
    gather_concat_kernel<<<(NN * 384 + 255) / 256, 256>>>(emb, ids, states, X0H, X0L);

    // ---- h0 = tanh(X0 @ W_init + b_init), fp32 + split bf16 ----
    {
        GP p = zeroGP();
        p.AH = X0H; p.AL = X0L; p.B1H = WinitH; p.B1L = WinitL;
        p.bias1 = b_init; p.C = hf; p.C1H = hH; p.C1L = hL;
        p.K = 384; p.lda = 384; p.ldb = 128; p.ldc = 128;
        p.mode = 3;
        gemm_k<<<dim3(NN / 128, 1, 1), 256, SMEM_BYTES>>>(p);
    }

    for (int t = 0; t < TT; t++) {
        // per-edge transforms: ho/hi = tanh(h @ W + b) -> split bf16, z=16 fused
        {
            GP p = zeroGP();
            p.AH = hH; p.AL = hL;
            p.B1H = WoutH; p.B1L = WoutL; p.B2H = WinH; p.B2L = WinL;
            p.bias1 = b_out; p.bias2 = b_in;
            p.C1H = hoH; p.C1L = hoL; p.C2H = hiH; p.C2L = hiL;
            p.K = HH; p.lda = HH; p.ldb = HH; p.ldc = HH;
            p.sB = (long)HH * HH; p.sC = (long)NN * HH;
            p.dual = 1; p.trans2 = 0; p.mode = 1; p.biasStride = HH;
            gemm_k<<<dim3(NN / 128, 1, 16), 256, SMEM_BYTES>>>(p);
        }
        // messages: z<8: adj[e] @ ho[e] -> msg[:, e*128]; z>=8: adj[e]^T @ hi[e] -> msg[:, 1024+e*128]
        {
            GP p = zeroGP();
            p.AH = adjH; p.AL = adjL;
            p.B1H = hoH; p.B1L = hoL; p.B2H = hiH; p.B2L = hiL;
            p.C1H = msgH; p.C1L = msgL;
            p.K = NN; p.lda = NN; p.ldb = HH; p.ldc = 2048;
            p.sA = (long)NN * NN; p.sB = (long)NN * HH;
            p.dual = 1; p.trans2 = 1; p.mode = 2;
            p.coff1 = 0; p.coff2 = 1024; p.cstride = 128;
            gemm_k<<<dim3(NN / 128, 1, 16), 256, SMEM_BYTES>>>(p);
        }
        // gi = msg @ Wx (fp32 out)
        {
            GP p = zeroGP();
            p.AH = msgH; p.AL = msgL; p.B1H = WxH; p.B1L = WxL;
            p.C = gi;
            p.K = 2048; p.lda = 2048; p.ldb = 384; p.ldc = 384;
            p.mode = 0;
            gemm_k<<<dim3(NN / 128, 3, 1), 256, SMEM_BYTES>>>(p);
        }
        // gh = h @ Wh (fp32 out)
        {
            GP p = zeroGP();
            p.AH = hH; p.AL = hL; p.B1H = WhH; p.B1L = WhL;
            p.C = gh;
            p.K = HH; p.lda = HH; p.ldb = 384; p.ldc = 384;
            p.mode = 0;
            gemm_k<<<dim3(NN / 128, 3, 1), 256, SMEM_BYTES>>>(p);
        }
        // GRU
        float* hnext = (t == TT - 1) ? out : hf;
        gru_kernel<<<NN, 128>>>(gi, gh, hf, bx, bh, gamma, beta, hnext, hH, hL);
    }
}

// round 3
// speedup vs baseline: 1.8189x; 1.0024x over previous
#include <cuda_runtime.h>
#include <cuda_bf16.h>
#include <mma.h>

using namespace nvcuda;

#define NN 4096
#define EMB 128
#define HH 128
#define EE 8
#define TT 2

typedef __nv_bfloat16 bf16;

// ---------------------------------------------------------------------------
// Scratch (device globals; allocation-free)
// ---------------------------------------------------------------------------
__device__ bf16 g_adjH[(long)EE * NN * NN];
__device__ bf16 g_adjL[(long)EE * NN * NN];
__device__ bf16 g_hoH[EE * NN * HH], g_hoL[EE * NN * HH];
__device__ bf16 g_hiH[EE * NN * HH], g_hiL[EE * NN * HH];
__device__ bf16 g_msgH[NN * 2048], g_msgL[NN * 2048];
__device__ bf16 g_hH[NN * HH], g_hL[NN * HH];
__device__ bf16 g_X0H[NN * 384], g_X0L[NN * 384];
__device__ bf16 g_WinitH[384 * HH], g_WinitL[384 * HH];
__device__ bf16 g_WoutH[EE * HH * HH], g_WoutL[EE * HH * HH];
__device__ bf16 g_WinH[EE * HH * HH], g_WinL[EE * HH * HH];
__device__ bf16 g_WxH[2048 * 384], g_WxL[2048 * 384];
__device__ bf16 g_WhH[HH * 384], g_WhL[HH * 384];
__device__ float g_hf[NN * HH];
__device__ float g_gi[NN * 384], g_gh[NN * 384];

__device__ __forceinline__ void split_bf16(float x, bf16& h, bf16& l) {
    h = __float2bfloat16(x);
    l = __float2bfloat16(x - __bfloat162float(h));
}

__device__ __forceinline__ void cp16(bf16* dst, const bf16* src) {
    unsigned d = (unsigned)__cvta_generic_to_shared(dst);
    asm volatile("cp.async.cg.shared.global [%0], [%1], 16;" :: "r"(d), "l"(src));
}
__device__ __forceinline__ void cp_commit() { asm volatile("cp.async.commit_group;"); }
template <int N> __device__ __forceinline__ void cp_wait() {
    asm volatile("cp.async.wait_group %0;" :: "n"(N));
}

// ---------------------------------------------------------------------------
// fp32 -> split bf16 conversion (vectorized, 4 elems/thread)
// ---------------------------------------------------------------------------
__global__ void split_kernel(const float4* __restrict__ x,
                             uint2* __restrict__ hOut, uint2* __restrict__ lOut,
                             long n4) {
    long i = (long)blockIdx.x * blockDim.x + threadIdx.x;
    if (i >= n4) return;
    float4 v = x[i];
    float vv[4] = {v.x, v.y, v.z, v.w};
    union { bf16 b[4]; uint2 u; } ph, pl;
#pragma unroll
    for (int j = 0; j < 4; j++) split_bf16(vv[j], ph.b[j], pl.b[j]);
    hOut[i] = ph.u;
    lOut[i] = pl.u;
}

// ---------------------------------------------------------------------------
// gather + concat -> split bf16 X0
// ---------------------------------------------------------------------------
__global__ void gather_concat_kernel(const float* __restrict__ emb,
                                     const int* __restrict__ ids,
                                     const float* __restrict__ states,
                                     bf16* __restrict__ XH, bf16* __restrict__ XL) {
    int i = blockIdx.x * blockDim.x + threadIdx.x;
    if (i >= NN * 384) return;
    int n = i / 384, c = i % 384;
    float v = (c < EMB) ? emb[(long)ids[n] * EMB + c]
                        : states[(long)n * (2 * EMB) + (c - EMB)];
    bf16 h, l;
    split_bf16(v, h, l);
    XH[i] = h;
    XL[i] = l;
}

// ---------------------------------------------------------------------------
// Pipelined split-bf16 GEMM, BM=BN=128, BK=32, 4 stages, 256 threads.
// modes: 0=fp32 C; 1=tanh(acc+bias)->split bf16; 2=split bf16; 3=tanh->fp32+split
// dual: z in [0,16), z>=8 uses B2/bias2/C2 and (optionally) transA.
// ---------------------------------------------------------------------------
struct GP {
    const bf16 *AH, *AL, *B1H, *B1L, *B2H, *B2L;
    const float *bias1, *bias2;
    float* C;
    bf16 *C1H, *C1L, *C2H, *C2L;
    int K, lda, ldb, ldc;
    long sA, sB, sC;
    int dual, trans2, mode;
    int coff1, coff2, cstride, biasStride;
};

#define STAGES 4
#define ASZ 5120     // elems: max(128*40, 32*136)
#define BSZ 4352     // elems: 32*136
#define STG (2 * ASZ + 2 * BSZ)
#define SMEM_BYTES (STAGES * STG * 2)

__global__ __launch_bounds__(256)
void gemm_k(GP p) {
    extern __shared__ char smemraw[];
    bf16* sm = (bf16*)smemraw;

    const int z = blockIdx.z;
    const bool second = p.dual && (z >= 8);
    const int e = p.dual ? (z & 7) : z;
    const int trans = second ? p.trans2 : 0;

    const bf16* AH = p.AH + (long)e * p.sA;
    const bf16* AL = p.AL + (long)e * p.sA;
    const bf16* BH = (second ? p.B2H : p.B1H) + (long)e * p.sB;
    const bf16* BL = (second ? p.B2L : p.B1L) + (long)e * p.sB;

    const int i0 = blockIdx.x * 128;
    const int j0 = blockIdx.y * 128;
    const int tid = threadIdx.x;
    const int wm = (tid >> 5) & 3;
    const int wn = tid >> 7;

    auto loadStage = [&](int s, int k0) {
        bf16* aH = sm + s * STG;
        bf16* aL = aH + ASZ;
        bf16* bH = aL + ASZ;
        bf16* bL = bH + BSZ;
        if (!trans) {
#pragma unroll
            for (int t = 0; t < 2; t++) {
                int idx = tid + t * 256;
                int r = idx >> 2, c = (idx & 3) * 8;
                cp16(aH + r * 40 + c, AH + (long)(i0 + r) * p.lda + k0 + c);
                cp16(aL + r * 40 + c, AL + (long)(i0 + r) * p.lda + k0 + c);
            }
        } else {
#pragma unroll
            for (int t = 0; t < 2; t++) {
                int idx = tid + t * 256;
                int r = idx >> 4, c = (idx & 15) * 8;
                cp16(aH + r * 136 + c, AH + (long)(k0 + r) * p.lda + i0 + c);
                cp16(aL + r * 136 + c, AL + (long)(k0 + r) * p.lda + i0 + c);
            }
        }
#pragma unroll
        for (int t = 0; t < 2; t++) {
            int idx = tid + t * 256;
            int r = idx >> 4, c = (idx & 15) * 8;
            cp16(bH + r * 136 + c, BH + (long)(k0 + r) * p.ldb + j0 + c);
            cp16(bL + r * 136 + c, BL + (long)(k0 + r) * p.ldb + j0 + c);
        }
    };

    wmma::fragment<wmma::accumulator, 16, 16, 16, float> acc[2][4];
#pragma unroll
    for (int m = 0; m < 2; m++)
#pragma unroll
        for (int n = 0; n < 4; n++)
            wmma::fill_fragment(acc[m][n], 0.0f);

    const int kIters = p.K / 32;
    for (int s = 0; s < STAGES - 1 && s < kIters; s++) {
        loadStage(s, s * 32);
        cp_commit();
    }

    for (int ki = 0; ki < kIters; ki++) {
        cp_wait<STAGES - 2>();
        __syncthreads();
        int ns = ki + STAGES - 1;
        if (ns < kIters) loadStage(ns % STAGES, ns * 32);
        cp_commit();

        bf16* aHB = sm + (ki % STAGES) * STG;
        bf16* aLB = aHB + ASZ;
        bf16* bHB = aLB + ASZ;
        bf16* bLB = bHB + BSZ;

        if (!trans) {
#pragma unroll
            for (int ks = 0; ks < 32; ks += 16) {
                wmma::fragment<wmma::matrix_a, 16, 16, 16, bf16, wmma::row_major> ah[2], al[2];
#pragma unroll
                for (int m = 0; m < 2; m++) {
                    wmma::load_matrix_sync(ah[m], aHB + (wm * 32 + m * 16) * 40 + ks, 40);
                    wmma::load_matrix_sync(al[m], aLB + (wm * 32 + m * 16) * 40 + ks, 40);
                }
#pragma unroll
                for (int n = 0; n < 4; n++) {
                    wmma::fragment<wmma::matrix_b, 16, 16, 16, bf16, wmma::row_major> bh_, bl_;
                    wmma::load_matrix_sync(bh_, bHB + ks * 136 + wn * 64 + n * 16, 136);
                    wmma::load_matrix_sync(bl_, bLB + ks * 136 + wn * 64 + n * 16, 136);
#pragma unroll
                    for (int m = 0; m < 2; m++) {
                        wmma::mma_sync(acc[m][n], ah[m], bh_, acc[m][n]);
                        wmma::mma_sync(acc[m][n], ah[m], bl_, acc[m][n]);
                        wmma::mma_sync(acc[m][n], al[m], bh_, acc[m][n]);
                    }
                }
            }
        } else {
#pragma unroll
            for (int ks = 0; ks < 32; ks += 16) {
                wmma::fragment<wmma::matrix_a, 16, 16, 16, bf16, wmma::col_major> ah[2], al[2];
#pragma unroll
                for (int m = 0; m < 2; m++) {
                    wmma::load_matrix_sync(ah[m], aHB + ks * 136 + wm * 32 + m * 16, 136);
                    wmma::load_matrix_sync(al[m], aLB + ks * 136 + wm * 32 + m * 16, 136);
                }
#pragma unroll
                for (int n = 0; n < 4; n++) {
                    wmma::fragment<wmma::matrix_b, 16, 16, 16, bf16, wmma::row_major> bh_, bl_;
                    wmma::load_matrix_sync(bh_, bHB + ks * 136 + wn * 64 + n * 16, 136);
                    wmma::load_matrix_sync(bl_, bLB + ks * 136 + wn * 64 + n * 16, 136);
#pragma unroll
                    for (int m = 0; m < 2; m++) {
                        wmma::mma_sync(acc[m][n], ah[m], bh_, acc[m][n]);
                        wmma::mma_sync(acc[m][n], ah[m], bl_, acc[m][n]);
                        wmma::mma_sync(acc[m][n], al[m], bh_, acc[m][n]);
                    }
                }
            }
        }
    }

    // ---- epilogue (reuse pipeline smem as fp32 staging [128][132]) ----
    cp_wait<0>();
    __syncthreads();
    float* st = (float*)smemraw;
#pragma unroll
    for (int m = 0; m < 2; m++)
#pragma unroll
        for (int n = 0; n < 4; n++)
            wmma::store_matrix_sync(st + (wm * 32 + m * 16) * 132 + wn * 64 + n * 16,
                                    acc[m][n], 132, wmma::mem_row_major);
    __syncthreads();

    const int colOff = (second ? p.coff2 : p.coff1) + e * p.cstride + j0;
    const long cbase = (long)e * p.sC;
    const float* bias = second ? p.bias2 : p.bias1;
    bf16* CH = (second && p.C2H) ? p.C2H : p.C1H;
    bf16* CL = (second && p.C2L) ? p.C2L : p.C1L;

#pragma unroll
    for (int t = 0; t < 16; t++) {
        int idx = tid + t * 256;
        int r = idx >> 5, c = (idx & 31) * 4;
        float4 v = *(float4*)(st + r * 132 + c);
        float vv[4] = {v.x, v.y, v.z, v.w};
        if (p.mode == 1 || p.mode == 3) {
#pragma unroll
            for (int j = 0; j < 4; j++)
                vv[j] = tanhf(vv[j] + bias[e * p.biasStride + j0 + c + j]);
        }
        long row = cbase + (long)(i0 + r) * p.ldc + colOff + c;
        if (p.mode == 0 || p.mode == 3)
            *(float4*)(p.C + row) = make_float4(vv[0], vv[1], vv[2], vv[3]);
        if (p.mode != 0) {
            union { bf16 b[4]; uint2 u; } ph, pl;
#pragma unroll
            for (int j = 0; j < 4; j++) split_bf16(vv[j], ph.b[j], pl.b[j]);
            *(uint2*)(CH + row) = ph.u;
            *(uint2*)(CL + row) = pl.u;
        }
    }
}

// ---------------------------------------------------------------------------
// GRU + LayerNorm, one block per node row, 128 threads
// ---------------------------------------------------------------------------
__device__ __forceinline__ float block_sum128(float v, float* red) {
#pragma unroll
    for (int o = 16; o; o >>= 1) v += __shfl_xor_sync(0xffffffffu, v, o);
    int lane = threadIdx.x & 31, w = threadIdx.x >> 5;
    if (lane == 0) red[w] = v;
    __syncthreads();
    float s = red[0] + red[1] + red[2] + red[3];
    __syncthreads();
    return s;
}

__global__ void gru_kernel(const float* __restrict__ gi, const float* __restrict__ gh,
                           const float* __restrict__ h,
                           const float* __restrict__ bx, const float* __restrict__ bh,
                           const float* __restrict__ gamma, const float* __restrict__ beta,
                           float* __restrict__ out,
                           bf16* __restrict__ outH, bf16* __restrict__ outL) {
    __shared__ float red[4];
    const int n = blockIdx.x;
    const int k = threadIdx.x;

    float gi0 = gi[(long)n * 384 + k];
    float gi1 = gi[(long)n * 384 + 128 + k];
    float gi2 = gi[(long)n * 384 + 256 + k];
    float gh0 = gh[(long)n * 384 + k];
    float gh1 = gh[(long)n * 384 + 128 + k];
    float gh2 = gh[(long)n * 384 + 256 + k];

    float xr = gi0 + bx[k]       + gh0 + bh[k];
    float xz = gi1 + bx[128 + k] + gh1 + bh[128 + k];
    float xi = gi2 + bx[256 + k];
    float xh = gh2 + bh[256 + k];

    float mean = block_sum128(xr, red) * (1.0f / 128.0f);
    float d = xr - mean;
    float var = block_sum128(d * d, red) * (1.0f / 128.0f);
    float yr = d * rsqrtf(var + 1e-5f) * gamma[k] + beta[k];
    float r = 1.0f / (1.0f + expf(-yr));

    mean = block_sum128(xz, red) * (1.0f / 128.0f);
    d = xz - mean;
    var = block_sum128(d * d, red) * (1.0f / 128.0f);
    float yz = d * rsqrtf(var + 1e-5f) * gamma[128 + k] + beta[128 + k];
    float z = 1.0f / (1.0f + expf(-yz));

    float xn = xi + r * xh;
    mean = block_sum128(xn, red) * (1.0f / 128.0f);
    d = xn - mean;
    var = block_sum128(d * d, red) * (1.0f / 128.0f);
    float yn = d * rsqrtf(var + 1e-5f) * gamma[256 + k] + beta[256 + k];
    float nn_ = tanhf(yn);

    float hv = h[(long)n * 128 + k];
    float o = (1.0f - z) * nn_ + z * hv;
    out[(long)n * 128 + k] = o;
    bf16 hh, ll;
    split_bf16(o, hh, ll);
    outH[(long)n * 128 + k] = hh;
    outL[(long)n * 128 + k] = ll;
}

// ---------------------------------------------------------------------------
// launch
// ---------------------------------------------------------------------------
static inline GP zeroGP() { GP p; memset(&p, 0, sizeof(p)); return p; }

extern "C" void kernel_launch(void* const* d_in, const int* in_sizes, int n_in,
                              void* d_out, int out_size) {
    (void)in_sizes; (void)n_in; (void)out_size;

    const float* adj    = (const float*)d_in[0];
    const float* states = (const float*)d_in[1];
    const int*   ids    = (const int*)  d_in[2];
    const float* emb    = (const float*)d_in[3];
    const float* W_init = (const float*)d_in[4];
    const float* b_init = (const float*)d_in[5];
    const float* W_out  = (const float*)d_in[6];
    const float* b_out  = (const float*)d_in[7];
    const float* W_in   = (const float*)d_in[8];
    const float* b_in   = (const float*)d_in[9];
    const float* Wx     = (const float*)d_in[10];
    const float* bx     = (const float*)d_in[11];
    const float* Wh     = (const float*)d_in[12];
    const float* bh     = (const float*)d_in[13];
    const float* gamma  = (const float*)d_in[14];
    const float* beta   = (const float*)d_in[15];
    float* out = (float*)d_out;

    bf16 *adjH, *adjL, *hoH, *hoL, *hiH, *hiL, *msgH, *msgL, *hH, *hL;
    bf16 *X0H, *X0L, *WinitH, *WinitL, *WoutH, *WoutL, *WinH, *WinL;
    bf16 *WxH, *WxL, *WhH, *WhL;
    float *hf, *gi, *gh;
    cudaGetSymbolAddress((void**)&adjH, g_adjH);
    cudaGetSymbolAddress((void**)&adjL, g_adjL);
    cudaGetSymbolAddress((void**)&hoH, g_hoH);
    cudaGetSymbolAddress((void**)&hoL, g_hoL);
    cudaGetSymbolAddress((void**)&hiH, g_hiH);
    cudaGetSymbolAddress((void**)&hiL, g_hiL);
    cudaGetSymbolAddress((void**)&msgH, g_msgH);
    cudaGetSymbolAddress((void**)&msgL, g_msgL);
    cudaGetSymbolAddress((void**)&hH, g_hH);
    cudaGetSymbolAddress((void**)&hL, g_hL);
    cudaGetSymbolAddress((void**)&X0H, g_X0H);
    cudaGetSymbolAddress((void**)&X0L, g_X0L);
    cudaGetSymbolAddress((void**)&WinitH, g_WinitH);
    cudaGetSymbolAddress((void**)&WinitL, g_WinitL);
    cudaGetSymbolAddress((void**)&WoutH, g_WoutH);
    cudaGetSymbolAddress((void**)&WoutL, g_WoutL);
    cudaGetSymbolAddress((void**)&WinH, g_WinH);
    cudaGetSymbolAddress((void**)&WinL, g_WinL);
    cudaGetSymbolAddress((void**)&WxH, g_WxH);
    cudaGetSymbolAddress((void**)&WxL, g_WxL);
    cudaGetSymbolAddress((void**)&WhH, g_WhH);
    cudaGetSymbolAddress((void**)&WhL, g_WhL);
    cudaGetSymbolAddress((void**)&hf, g_hf);
    cudaGetSymbolAddress((void**)&gi, g_gi);
    cudaGetSymbolAddress((void**)&gh, g_gh);

    cudaFuncSetAttribute(gemm_k, cudaFuncAttributeMaxDynamicSharedMemorySize, SMEM_BYTES);

    // ---- preconvert operands to split bf16 ----
    {
        long n4 = (long)EE * NN * NN / 4;
        split_kernel<<<(unsigned)((n4 + 255) / 256), 256>>>((const float4*)adj, (uint2*)adjH, (uint2*)adjL, n4);
    }
    split_kernel<<<(384 * HH / 4 + 255) / 256, 256>>>((const float4*)W_init, (uint2*)WinitH, (uint2*)WinitL, 384 * HH / 4);
    split_kernel<<<(EE * HH * HH / 4 + 255) / 256, 256>>>((const float4*)W_out, (uint2*)WoutH, (uint2*)WoutL, EE * HH * HH / 4);
    split_kernel<<<(EE * HH * HH / 4 + 255) / 256, 256>>>((const float4*)W_in, (uint2*)WinH, (uint2*)WinL, EE * HH * HH / 4);
    split_kernel<<<(2048 * 384 / 4 + 255) / 256, 256>>>((const float4*)Wx, (uint2*)WxH, (uint2*)WxL, 2048 * 384 / 4);
    split_kernel<<<(HH * 384 / 4 + 255) / 256, 256>>>((const float4*)Wh, (uint2*)WhH, (uint2*)WhL, HH * 384 / 4);
    gather_concat_kernel<<<(NN * 384 + 255) / 256, 256>>>(emb, ids, states, X0H, X0L);

    // ---- h0 = tanh(X0 @ W_init + b_init), fp32 + split bf16 ----
    {
        GP p = zeroGP();
        p.AH = X0H; p.AL = X0L; p.B1H = WinitH; p.B1L = WinitL;
        p.bias1 = b_init; p.C = hf; p.C1H = hH; p.C1L = hL;
        p.K = 384; p.lda = 384; p.ldb = 128; p.ldc = 128;
        p.mode = 3;
        gemm_k<<<dim3(NN / 128, 1, 1), 256, SMEM_BYTES>>>(p);
    }

    for (int t = 0; t < TT; t++) {
        // per-edge transforms: ho/hi = tanh(h @ W + b) -> split bf16, z=16 fused
        {
            GP p = zeroGP();
            p.AH = hH; p.AL = hL;
            p.B1H = WoutH; p.B1L = WoutL; p.B2H = WinH; p.B2L = WinL;
            p.bias1 = b_out; p.bias2 = b_in;
            p.C1H = hoH; p.C1L = hoL; p.C2H = hiH; p.C2L = hiL;
            p.K = HH; p.lda = HH; p.ldb = HH; p.ldc = HH;
            p.sB = (long)HH * HH; p.sC = (long)NN * HH;
            p.dual = 1; p.trans2 = 0; p.mode = 1; p.biasStride = HH;
            gemm_k<<<dim3(NN / 128, 1, 16), 256, SMEM_BYTES>>>(p);
        }
        // messages: z<8: adj[e] @ ho[e] -> msg[:, e*128]; z>=8: adj[e]^T @ hi[e] -> msg[:, 1024+e*128]
        {
            GP p = zeroGP();
            p.AH = adjH; p.AL = adjL;
            p.B1H = hoH; p.B1L = hoL; p.B2H = hiH; p.B2L = hiL;
            p.C1H = msgH; p.C1L = msgL;
            p.K = NN; p.lda = NN; p.ldb = HH; p.ldc = 2048;
            p.sA = (long)NN * NN; p.sB = (long)NN * HH;
            p.dual = 1; p.trans2 = 1; p.mode = 2;
            p.coff1 = 0; p.coff2 = 1024; p.cstride = 128;
            gemm_k<<<dim3(NN / 128, 1, 16), 256, SMEM_BYTES>>>(p);
        }
        // gi = msg @ Wx (fp32 out)
        {
            GP p = zeroGP();
            p.AH = msgH; p.AL = msgL; p.B1H = WxH; p.B1L = WxL;
            p.C = gi;
            p.K = 2048; p.lda = 2048; p.ldb = 384; p.ldc = 384;
            p.mode = 0;
            gemm_k<<<dim3(NN / 128, 3, 1), 256, SMEM_BYTES>>>(p);
        }
        // gh = h @ Wh (fp32 out)
        {
            GP p = zeroGP();
            p.AH = hH; p.AL = hL; p.B1H = WhH; p.B1L = WhL;
            p.C = gh;
            p.K = HH; p.lda = HH; p.ldb = 384; p.ldc = 384;
            p.mode = 0;
            gemm_k<<<dim3(NN / 128, 3, 1), 256, SMEM_BYTES>>>(p);
        }
        // GRU
        float* hnext = (t == TT - 1) ? out : hf;
        gru_kernel<<<NN, 128>>>(gi, gh, hf, bx, bh, gamma, beta, hnext, hH, hL);
    }
}